// round 5
// baseline (speedup 1.0000x reference)
#include <cuda_runtime.h>
#include <cuda_fp16.h>
#include <cstdint>
#include <cstddef>

// Problem constants: N=100000, D_IN=D_OUT=256, E=3.2M
#define MAXN 100352
#define MAXE 3200000
#define D    256

// Scratch (device globals; allocation is forbidden)
__device__ __align__(16) __half g_h2[(size_t)MAXN * D];  // fp16(x @ W^T), UNscaled
__device__ float g_drs[MAXN];
__device__ int   g_cnt[MAXN];
__device__ int   g_excl[MAXN];
__device__ int   g_blksum[512];
__device__ int   g_rowptr[MAXN + 1];
__device__ int   g_off[MAXN];
__device__ int   g_col[MAXE];

__device__ __forceinline__ uint32_t smem_u32(const void* p) {
    return (uint32_t)__cvta_generic_to_shared(p);
}

// ---------------------------------------------------------------------------
// Degree histogram
// ---------------------------------------------------------------------------
__global__ void cnt_zero(int N) {
    int i = blockIdx.x * blockDim.x + threadIdx.x;
    if (i < N) g_cnt[i] = 0;
}

__global__ void cnt_edges(const int* __restrict__ src, int E) {
    int e = blockIdx.x * blockDim.x + threadIdx.x;
    if (e < E) atomicAdd(&g_cnt[src[e]], 1);
}

// ---------------------------------------------------------------------------
// Prefix sum over g_cnt -> g_rowptr (+ fused drs = rsqrt(deg+1))
// ---------------------------------------------------------------------------
__global__ void scan_phase1(int N) {
    __shared__ int sh[256];
    int i = blockIdx.x * 256 + threadIdx.x;
    int v = (i < N) ? g_cnt[i] : 0;
    if (i < N) g_drs[i] = rsqrtf((float)v + 1.0f);   // fused normalization
    sh[threadIdx.x] = v;
    __syncthreads();
#pragma unroll
    for (int off = 1; off < 256; off <<= 1) {
        int t = (threadIdx.x >= off) ? sh[threadIdx.x - off] : 0;
        __syncthreads();
        sh[threadIdx.x] += t;
        __syncthreads();
    }
    if (i < N) g_excl[i] = sh[threadIdx.x] - v;
    if (threadIdx.x == 255) g_blksum[blockIdx.x] = sh[255];
}

__global__ void scan_phase2(int nb) {
    __shared__ int sh[512];
    int t = threadIdx.x;
    int v = (t < nb) ? g_blksum[t] : 0;
    sh[t] = v;
    __syncthreads();
#pragma unroll
    for (int off = 1; off < 512; off <<= 1) {
        int u = (t >= off) ? sh[t - off] : 0;
        __syncthreads();
        sh[t] += u;
        __syncthreads();
    }
    if (t < nb) g_blksum[t] = sh[t] - v;
}

__global__ void scan_phase3(int N, int E) {
    int i = blockIdx.x * 256 + threadIdx.x;
    if (i < N) {
        int r = g_excl[i] + g_blksum[blockIdx.x];
        g_rowptr[i] = r;
        g_off[i] = r;
    }
    if (i == 0) g_rowptr[N] = E;
}

__global__ void build_col(const int* __restrict__ src, const int* __restrict__ dst, int E) {
    int e = blockIdx.x * blockDim.x + threadIdx.x;
    if (e < E) {
        int p = atomicAdd(&g_off[src[e]], 1);
        g_col[p] = dst[e];
    }
}

// ---------------------------------------------------------------------------
// Pipelined tensor-core HGEMM: g_h2 = fp16(A @ W^T)   (no drs dependency)
// 128x128 block tile, BK=16, 8 warps (2x4), register-prefetch pipeline.
// ---------------------------------------------------------------------------
__global__ void __launch_bounds__(256, 2) hgemm_abt(const float* __restrict__ A,
                                                    const float* __restrict__ Wm,
                                                    int M) {
    __shared__ __align__(16) __half As[128][24];   // 48B row stride
    __shared__ __align__(16) __half Bs[128][24];

    const int tid  = threadIdx.x;
    const int lane = tid & 31;
    const int wid  = tid >> 5;
    const int wm   = wid >> 2;
    const int wn   = wid & 3;
    const int brow = blockIdx.y * 128;
    const int bcol = blockIdx.x * 128;

    const int r0c = (tid)       >> 2;
    const int r1c = (tid + 256) >> 2;
    const int cf0 = (tid & 3) * 4;

    float acc[4][4][4];
#pragma unroll
    for (int mt = 0; mt < 4; mt++)
#pragma unroll
        for (int nt = 0; nt < 4; nt++)
#pragma unroll
            for (int q = 0; q < 4; q++) acc[mt][nt][q] = 0.0f;

    float4 pa0, pa1, pb0, pb1;
    {
        int ga0 = brow + r0c, ga1 = brow + r1c;
        pa0 = (ga0 < M) ? *reinterpret_cast<const float4*>(A + (size_t)ga0 * 256 + cf0)
                        : make_float4(0.f, 0.f, 0.f, 0.f);
        pa1 = (ga1 < M) ? *reinterpret_cast<const float4*>(A + (size_t)ga1 * 256 + cf0)
                        : make_float4(0.f, 0.f, 0.f, 0.f);
        pb0 = *reinterpret_cast<const float4*>(Wm + (size_t)(bcol + r0c) * 256 + cf0);
        pb1 = *reinterpret_cast<const float4*>(Wm + (size_t)(bcol + r1c) * 256 + cf0);
    }

#pragma unroll 4
    for (int k0 = 0; k0 < 256; k0 += 16) {
        {
            __half2* da0 = reinterpret_cast<__half2*>(&As[r0c][cf0]);
            da0[0] = __floats2half2_rn(pa0.x, pa0.y);
            da0[1] = __floats2half2_rn(pa0.z, pa0.w);
            __half2* da1 = reinterpret_cast<__half2*>(&As[r1c][cf0]);
            da1[0] = __floats2half2_rn(pa1.x, pa1.y);
            da1[1] = __floats2half2_rn(pa1.z, pa1.w);
            __half2* db0 = reinterpret_cast<__half2*>(&Bs[r0c][cf0]);
            db0[0] = __floats2half2_rn(pb0.x, pb0.y);
            db0[1] = __floats2half2_rn(pb0.z, pb0.w);
            __half2* db1 = reinterpret_cast<__half2*>(&Bs[r1c][cf0]);
            db1[0] = __floats2half2_rn(pb1.x, pb1.y);
            db1[1] = __floats2half2_rn(pb1.z, pb1.w);
        }
        __syncthreads();

        if (k0 + 16 < 256) {
            int kn = k0 + 16;
            int ga0 = brow + r0c, ga1 = brow + r1c;
            pa0 = (ga0 < M) ? *reinterpret_cast<const float4*>(A + (size_t)ga0 * 256 + kn + cf0)
                            : make_float4(0.f, 0.f, 0.f, 0.f);
            pa1 = (ga1 < M) ? *reinterpret_cast<const float4*>(A + (size_t)ga1 * 256 + kn + cf0)
                            : make_float4(0.f, 0.f, 0.f, 0.f);
            pb0 = *reinterpret_cast<const float4*>(Wm + (size_t)(bcol + r0c) * 256 + kn + cf0);
            pb1 = *reinterpret_cast<const float4*>(Wm + (size_t)(bcol + r1c) * 256 + kn + cf0);
        }

        uint32_t a[4][4], b[4][2];
#pragma unroll
        for (int mt = 0; mt < 4; mt++) {
            uint32_t addr = smem_u32(&As[wm * 64 + mt * 16 + (lane & 15)][(lane >> 4) * 8]);
            asm volatile("ldmatrix.sync.aligned.m8n8.x4.shared.b16 {%0,%1,%2,%3}, [%4];"
                         : "=r"(a[mt][0]), "=r"(a[mt][1]), "=r"(a[mt][2]), "=r"(a[mt][3])
                         : "r"(addr));
        }
#pragma unroll
        for (int nt = 0; nt < 4; nt++) {
            int l16 = lane & 15;
            uint32_t addr = smem_u32(&Bs[wn * 32 + nt * 8 + (l16 & 7)][(l16 >> 3) * 8]);
            asm volatile("ldmatrix.sync.aligned.m8n8.x2.shared.b16 {%0,%1}, [%2];"
                         : "=r"(b[nt][0]), "=r"(b[nt][1])
                         : "r"(addr));
        }
#pragma unroll
        for (int mt = 0; mt < 4; mt++)
#pragma unroll
            for (int nt = 0; nt < 4; nt++)
                asm volatile(
                    "mma.sync.aligned.m16n8k16.row.col.f32.f16.f16.f32 "
                    "{%0,%1,%2,%3},{%4,%5,%6,%7},{%8,%9},{%0,%1,%2,%3};"
                    : "+f"(acc[mt][nt][0]), "+f"(acc[mt][nt][1]),
                      "+f"(acc[mt][nt][2]), "+f"(acc[mt][nt][3])
                    : "r"(a[mt][0]), "r"(a[mt][1]), "r"(a[mt][2]), "r"(a[mt][3]),
                      "r"(b[nt][0]), "r"(b[nt][1]));
        __syncthreads();
    }

    // Epilogue: plain fp16 store (no scaling — drs applied in aggregate).
    const int tg = lane >> 2, tq = lane & 3;
#pragma unroll
    for (int mt = 0; mt < 4; mt++) {
        int r0 = brow + wm * 64 + mt * 16 + tg;
        int r1 = r0 + 8;
#pragma unroll
        for (int nt = 0; nt < 4; nt++) {
            int c = bcol + wn * 32 + nt * 8 + tq * 2;
            if (r0 < M)
                *reinterpret_cast<__half2*>(g_h2 + (size_t)r0 * D + c) =
                    __floats2half2_rn(acc[mt][nt][0], acc[mt][nt][1]);
            if (r1 < M)
                *reinterpret_cast<__half2*>(g_h2 + (size_t)r1 * D + c) =
                    __floats2half2_rn(acc[mt][nt][2], acc[mt][nt][3]);
        }
    }
}

// ---------------------------------------------------------------------------
// Aggregation: one warp per node, 4-way unrolled gather, per-neighbor drs.
// out[i] = drs[i] * ( drs[i]*h[i] + sum_j drs[j]*h[j] )
// ---------------------------------------------------------------------------
__global__ void __launch_bounds__(256) aggregate(float* __restrict__ out, int N) {
    int warp = (blockIdx.x * blockDim.x + threadIdx.x) >> 5;
    int lane = threadIdx.x & 31;
    if (warp >= N) return;
    const int i = warp;
    const float ri = g_drs[i];

    float acc[8];
    {   // self loop: drs[i] * h[i]
        uint4 w = *reinterpret_cast<const uint4*>(g_h2 + (size_t)i * D + lane * 8);
        const __half2* hv = reinterpret_cast<const __half2*>(&w);
#pragma unroll
        for (int q = 0; q < 4; q++) {
            float2 f = __half22float2(hv[q]);
            acc[2*q + 0] = f.x * ri;
            acc[2*q + 1] = f.y * ri;
        }
    }

    int s = g_rowptr[i];
    int e = g_rowptr[i + 1];
    for (int b = s; b < e; b += 32) {
        int   nidx = (b + lane < e) ? g_col[b + lane] : 0;
        float nrs  = g_drs[nidx];
        int cnt = min(32, e - b);
        int t = 0;
        for (; t + 4 <= cnt; t += 4) {
            int   j0 = __shfl_sync(0xffffffffu, nidx, t + 0);
            int   j1 = __shfl_sync(0xffffffffu, nidx, t + 1);
            int   j2 = __shfl_sync(0xffffffffu, nidx, t + 2);
            int   j3 = __shfl_sync(0xffffffffu, nidx, t + 3);
            float r0 = __shfl_sync(0xffffffffu, nrs,  t + 0);
            float r1 = __shfl_sync(0xffffffffu, nrs,  t + 1);
            float r2 = __shfl_sync(0xffffffffu, nrs,  t + 2);
            float r3 = __shfl_sync(0xffffffffu, nrs,  t + 3);
            uint4 w0 = *reinterpret_cast<const uint4*>(g_h2 + (size_t)j0 * D + lane * 8);
            uint4 w1 = *reinterpret_cast<const uint4*>(g_h2 + (size_t)j1 * D + lane * 8);
            uint4 w2 = *reinterpret_cast<const uint4*>(g_h2 + (size_t)j2 * D + lane * 8);
            uint4 w3 = *reinterpret_cast<const uint4*>(g_h2 + (size_t)j3 * D + lane * 8);
            const __half2* h0 = reinterpret_cast<const __half2*>(&w0);
            const __half2* h1 = reinterpret_cast<const __half2*>(&w1);
            const __half2* h2 = reinterpret_cast<const __half2*>(&w2);
            const __half2* h3 = reinterpret_cast<const __half2*>(&w3);
#pragma unroll
            for (int q = 0; q < 4; q++) {
                float2 f0 = __half22float2(h0[q]);
                float2 f1 = __half22float2(h1[q]);
                float2 f2 = __half22float2(h2[q]);
                float2 f3 = __half22float2(h3[q]);
                acc[2*q + 0] += f0.x * r0 + f1.x * r1 + f2.x * r2 + f3.x * r3;
                acc[2*q + 1] += f0.y * r0 + f1.y * r1 + f2.y * r2 + f3.y * r3;
            }
        }
        for (; t < cnt; t++) {
            int   j  = __shfl_sync(0xffffffffu, nidx, t);
            float rj = __shfl_sync(0xffffffffu, nrs,  t);
            uint4 w = *reinterpret_cast<const uint4*>(g_h2 + (size_t)j * D + lane * 8);
            const __half2* hv = reinterpret_cast<const __half2*>(&w);
#pragma unroll
            for (int q = 0; q < 4; q++) {
                float2 f = __half22float2(hv[q]);
                acc[2*q + 0] += f.x * rj;
                acc[2*q + 1] += f.y * rj;
            }
        }
    }

    float4 v0 = make_float4(acc[0]*ri, acc[1]*ri, acc[2]*ri, acc[3]*ri);
    float4 v1 = make_float4(acc[4]*ri, acc[5]*ri, acc[6]*ri, acc[7]*ri);
    float* orow = out + (size_t)i * D + lane * 8;
    *reinterpret_cast<float4*>(orow)     = v0;
    *reinterpret_cast<float4*>(orow + 4) = v1;
}

// ---------------------------------------------------------------------------
// Launch: fork/join two parallel branches (CSR build || GEMM) then aggregate.
// ---------------------------------------------------------------------------
extern "C" void kernel_launch(void* const* d_in, const int* in_sizes, int n_in,
                              void* d_out, int out_size) {
    const float* x  = (const float*)d_in[0];   // [N,256]
    const float* W  = (const float*)d_in[1];   // [256,256]
    const int*   ei = (const int*)d_in[2];     // [2,E]

    int N = in_sizes[0] / D;
    int E = in_sizes[2] / 2;
    const int* src = ei;
    const int* dst = ei + E;
    float* out = (float*)d_out;

    int nbN = (N + 255) / 256;
    int nbE = (E + 255) / 256;

    // Persistent side stream + events (host handles only; created once).
    static cudaStream_t s2 = nullptr;
    static cudaEvent_t evFork = nullptr, evJoin = nullptr;
    if (s2 == nullptr) {
        cudaStreamCreateWithFlags(&s2, cudaStreamNonBlocking);
        cudaEventCreateWithFlags(&evFork, cudaEventDisableTiming);
        cudaEventCreateWithFlags(&evJoin, cudaEventDisableTiming);
    }

    // Fork: GEMM branch on s2 (independent of the degree/CSR chain).
    cudaEventRecord(evFork, 0);
    cudaStreamWaitEvent(s2, evFork, 0);
    {
        dim3 grid(D / 128, (N + 127) / 128);
        hgemm_abt<<<grid, 256, 0, s2>>>(x, W, N);
    }
    cudaEventRecord(evJoin, s2);

    // Main branch: degree histogram -> scan -> CSR fill.
    cnt_zero   <<<nbN, 256>>>(N);
    cnt_edges  <<<nbE, 256>>>(src, E);
    scan_phase1<<<nbN, 256>>>(N);
    scan_phase2<<<1,   512>>>(nbN);
    scan_phase3<<<nbN, 256>>>(N, E);
    build_col  <<<nbE, 256>>>(src, dst, E);

    // Join: aggregate needs both h2 and the CSR.
    cudaStreamWaitEvent(0, evJoin, 0);
    aggregate<<<(N + 7) / 8, 256>>>(out, N);
}

// round 6
// speedup vs baseline: 1.0776x; 1.0776x over previous
#include <cuda_runtime.h>
#include <cuda_fp16.h>
#include <cstdint>
#include <cstddef>

// Problem constants: N=100000, D_IN=D_OUT=256, E=3.2M
#define MAXN 100352
#define MAXE 3200000
#define D    256

// Scratch (device globals; allocation is forbidden)
__device__ __align__(16) __half g_h2[(size_t)MAXN * D];  // drs[j] * (x@W^T)[j], fp16
__device__ float g_drs[MAXN];
__device__ int   g_cnt[MAXN];
__device__ int   g_excl[MAXN];
__device__ int   g_blksum[512];
__device__ int   g_rowptr[MAXN + 1];
__device__ int   g_off[MAXN];
__device__ int   g_col[MAXE];

__device__ __forceinline__ uint32_t smem_u32(const void* p) {
    return (uint32_t)__cvta_generic_to_shared(p);
}

// ---------------------------------------------------------------------------
// Degree histogram
// ---------------------------------------------------------------------------
__global__ void cnt_zero(int N) {
    int i = blockIdx.x * blockDim.x + threadIdx.x;
    if (i < N) g_cnt[i] = 0;
}

__global__ void cnt_edges(const int* __restrict__ src, int E) {
    int e = blockIdx.x * blockDim.x + threadIdx.x;
    if (e < E) atomicAdd(&g_cnt[src[e]], 1);
}

// ---------------------------------------------------------------------------
// Prefix sum over g_cnt -> g_rowptr (+ fused drs = rsqrt(deg+1))
// ---------------------------------------------------------------------------
__global__ void scan_phase1(int N) {
    __shared__ int sh[256];
    int i = blockIdx.x * 256 + threadIdx.x;
    int v = (i < N) ? g_cnt[i] : 0;
    if (i < N) g_drs[i] = rsqrtf((float)v + 1.0f);   // fused normalization
    sh[threadIdx.x] = v;
    __syncthreads();
#pragma unroll
    for (int off = 1; off < 256; off <<= 1) {
        int t = (threadIdx.x >= off) ? sh[threadIdx.x - off] : 0;
        __syncthreads();
        sh[threadIdx.x] += t;
        __syncthreads();
    }
    if (i < N) g_excl[i] = sh[threadIdx.x] - v;
    if (threadIdx.x == 255) g_blksum[blockIdx.x] = sh[255];
}

__global__ void scan_phase2(int nb) {
    __shared__ int sh[512];
    int t = threadIdx.x;
    int v = (t < nb) ? g_blksum[t] : 0;
    sh[t] = v;
    __syncthreads();
#pragma unroll
    for (int off = 1; off < 512; off <<= 1) {
        int u = (t >= off) ? sh[t - off] : 0;
        __syncthreads();
        sh[t] += u;
        __syncthreads();
    }
    if (t < nb) g_blksum[t] = sh[t] - v;
}

__global__ void scan_phase3(int N, int E) {
    int i = blockIdx.x * 256 + threadIdx.x;
    if (i < N) {
        int r = g_excl[i] + g_blksum[blockIdx.x];
        g_rowptr[i] = r;
        g_off[i] = r;
    }
    if (i == 0) g_rowptr[N] = E;
}

__global__ void build_col(const int* __restrict__ src, const int* __restrict__ dst, int E) {
    int e = blockIdx.x * blockDim.x + threadIdx.x;
    if (e < E) {
        int p = atomicAdd(&g_off[src[e]], 1);
        g_col[p] = dst[e];
    }
}

// ---------------------------------------------------------------------------
// Pipelined tensor-core HGEMM: g_h2 = fp16( drs[i] * (A @ W^T) )
// 128x128 block tile, BK=16, 8 warps (2x4), register-prefetch pipeline.
// ---------------------------------------------------------------------------
__global__ void __launch_bounds__(256, 2) hgemm_abt(const float* __restrict__ A,
                                                    const float* __restrict__ Wm,
                                                    int M) {
    __shared__ __align__(16) __half As[128][24];   // 48B row stride
    __shared__ __align__(16) __half Bs[128][24];

    const int tid  = threadIdx.x;
    const int lane = tid & 31;
    const int wid  = tid >> 5;
    const int wm   = wid >> 2;
    const int wn   = wid & 3;
    const int brow = blockIdx.y * 128;
    const int bcol = blockIdx.x * 128;

    const int r0c = (tid)       >> 2;
    const int r1c = (tid + 256) >> 2;
    const int cf0 = (tid & 3) * 4;

    float acc[4][4][4];
#pragma unroll
    for (int mt = 0; mt < 4; mt++)
#pragma unroll
        for (int nt = 0; nt < 4; nt++)
#pragma unroll
            for (int q = 0; q < 4; q++) acc[mt][nt][q] = 0.0f;

    float4 pa0, pa1, pb0, pb1;
    {
        int ga0 = brow + r0c, ga1 = brow + r1c;
        pa0 = (ga0 < M) ? *reinterpret_cast<const float4*>(A + (size_t)ga0 * 256 + cf0)
                        : make_float4(0.f, 0.f, 0.f, 0.f);
        pa1 = (ga1 < M) ? *reinterpret_cast<const float4*>(A + (size_t)ga1 * 256 + cf0)
                        : make_float4(0.f, 0.f, 0.f, 0.f);
        pb0 = *reinterpret_cast<const float4*>(Wm + (size_t)(bcol + r0c) * 256 + cf0);
        pb1 = *reinterpret_cast<const float4*>(Wm + (size_t)(bcol + r1c) * 256 + cf0);
    }

#pragma unroll 4
    for (int k0 = 0; k0 < 256; k0 += 16) {
        {
            __half2* da0 = reinterpret_cast<__half2*>(&As[r0c][cf0]);
            da0[0] = __floats2half2_rn(pa0.x, pa0.y);
            da0[1] = __floats2half2_rn(pa0.z, pa0.w);
            __half2* da1 = reinterpret_cast<__half2*>(&As[r1c][cf0]);
            da1[0] = __floats2half2_rn(pa1.x, pa1.y);
            da1[1] = __floats2half2_rn(pa1.z, pa1.w);
            __half2* db0 = reinterpret_cast<__half2*>(&Bs[r0c][cf0]);
            db0[0] = __floats2half2_rn(pb0.x, pb0.y);
            db0[1] = __floats2half2_rn(pb0.z, pb0.w);
            __half2* db1 = reinterpret_cast<__half2*>(&Bs[r1c][cf0]);
            db1[0] = __floats2half2_rn(pb1.x, pb1.y);
            db1[1] = __floats2half2_rn(pb1.z, pb1.w);
        }
        __syncthreads();

        if (k0 + 16 < 256) {
            int kn = k0 + 16;
            int ga0 = brow + r0c, ga1 = brow + r1c;
            pa0 = (ga0 < M) ? *reinterpret_cast<const float4*>(A + (size_t)ga0 * 256 + kn + cf0)
                            : make_float4(0.f, 0.f, 0.f, 0.f);
            pa1 = (ga1 < M) ? *reinterpret_cast<const float4*>(A + (size_t)ga1 * 256 + kn + cf0)
                            : make_float4(0.f, 0.f, 0.f, 0.f);
            pb0 = *reinterpret_cast<const float4*>(Wm + (size_t)(bcol + r0c) * 256 + kn + cf0);
            pb1 = *reinterpret_cast<const float4*>(Wm + (size_t)(bcol + r1c) * 256 + kn + cf0);
        }

        uint32_t a[4][4], b[4][2];
#pragma unroll
        for (int mt = 0; mt < 4; mt++) {
            uint32_t addr = smem_u32(&As[wm * 64 + mt * 16 + (lane & 15)][(lane >> 4) * 8]);
            asm volatile("ldmatrix.sync.aligned.m8n8.x4.shared.b16 {%0,%1,%2,%3}, [%4];"
                         : "=r"(a[mt][0]), "=r"(a[mt][1]), "=r"(a[mt][2]), "=r"(a[mt][3])
                         : "r"(addr));
        }
#pragma unroll
        for (int nt = 0; nt < 4; nt++) {
            int l16 = lane & 15;
            uint32_t addr = smem_u32(&Bs[wn * 32 + nt * 8 + (l16 & 7)][(l16 >> 3) * 8]);
            asm volatile("ldmatrix.sync.aligned.m8n8.x2.shared.b16 {%0,%1}, [%2];"
                         : "=r"(b[nt][0]), "=r"(b[nt][1])
                         : "r"(addr));
        }
#pragma unroll
        for (int mt = 0; mt < 4; mt++)
#pragma unroll
            for (int nt = 0; nt < 4; nt++)
                asm volatile(
                    "mma.sync.aligned.m16n8k16.row.col.f32.f16.f16.f32 "
                    "{%0,%1,%2,%3},{%4,%5,%6,%7},{%8,%9},{%0,%1,%2,%3};"
                    : "+f"(acc[mt][nt][0]), "+f"(acc[mt][nt][1]),
                      "+f"(acc[mt][nt][2]), "+f"(acc[mt][nt][3])
                    : "r"(a[mt][0]), "r"(a[mt][1]), "r"(a[mt][2]), "r"(a[mt][3]),
                      "r"(b[nt][0]), "r"(b[nt][1]));
        __syncthreads();
    }

    // Epilogue: scale rows by drs (ready: GEMM launches after scan_phase1).
    const int tg = lane >> 2, tq = lane & 3;
#pragma unroll
    for (int mt = 0; mt < 4; mt++) {
        int r0 = brow + wm * 64 + mt * 16 + tg;
        int r1 = r0 + 8;
        float s0 = (r0 < M) ? g_drs[r0] : 0.f;
        float s1 = (r1 < M) ? g_drs[r1] : 0.f;
#pragma unroll
        for (int nt = 0; nt < 4; nt++) {
            int c = bcol + wn * 32 + nt * 8 + tq * 2;
            if (r0 < M)
                *reinterpret_cast<__half2*>(g_h2 + (size_t)r0 * D + c) =
                    __floats2half2_rn(acc[mt][nt][0] * s0, acc[mt][nt][1] * s0);
            if (r1 < M)
                *reinterpret_cast<__half2*>(g_h2 + (size_t)r1 * D + c) =
                    __floats2half2_rn(acc[mt][nt][2] * s1, acc[mt][nt][3] * s1);
        }
    }
}

// ---------------------------------------------------------------------------
// Aggregation (R4 version): one warp per node, 4-way unrolled gather.
// out[i] = drs[i] * ( h2[i] + sum_{j in adj(i)} h2[j] ),  h2 prescaled by drs.
// ---------------------------------------------------------------------------
__global__ void __launch_bounds__(256) aggregate(float* __restrict__ out, int N) {
    int warp = (blockIdx.x * blockDim.x + threadIdx.x) >> 5;
    int lane = threadIdx.x & 31;
    if (warp >= N) return;
    const int i = warp;

    float acc[8];
    {   // self loop
        uint4 w = *reinterpret_cast<const uint4*>(g_h2 + (size_t)i * D + lane * 8);
        const __half2* hv = reinterpret_cast<const __half2*>(&w);
#pragma unroll
        for (int q = 0; q < 4; q++) {
            float2 f = __half22float2(hv[q]);
            acc[2*q + 0] = f.x;
            acc[2*q + 1] = f.y;
        }
    }

    int s = g_rowptr[i];
    int e = g_rowptr[i + 1];
    for (int b = s; b < e; b += 32) {
        int nidx = (b + lane < e) ? g_col[b + lane] : 0;
        int cnt = min(32, e - b);
        int t = 0;
        for (; t + 4 <= cnt; t += 4) {
            int j0 = __shfl_sync(0xffffffffu, nidx, t + 0);
            int j1 = __shfl_sync(0xffffffffu, nidx, t + 1);
            int j2 = __shfl_sync(0xffffffffu, nidx, t + 2);
            int j3 = __shfl_sync(0xffffffffu, nidx, t + 3);
            uint4 w0 = *reinterpret_cast<const uint4*>(g_h2 + (size_t)j0 * D + lane * 8);
            uint4 w1 = *reinterpret_cast<const uint4*>(g_h2 + (size_t)j1 * D + lane * 8);
            uint4 w2 = *reinterpret_cast<const uint4*>(g_h2 + (size_t)j2 * D + lane * 8);
            uint4 w3 = *reinterpret_cast<const uint4*>(g_h2 + (size_t)j3 * D + lane * 8);
            const __half2* h0 = reinterpret_cast<const __half2*>(&w0);
            const __half2* h1 = reinterpret_cast<const __half2*>(&w1);
            const __half2* h2 = reinterpret_cast<const __half2*>(&w2);
            const __half2* h3 = reinterpret_cast<const __half2*>(&w3);
#pragma unroll
            for (int q = 0; q < 4; q++) {
                float2 f0 = __half22float2(h0[q]);
                float2 f1 = __half22float2(h1[q]);
                float2 f2 = __half22float2(h2[q]);
                float2 f3 = __half22float2(h3[q]);
                acc[2*q + 0] += (f0.x + f1.x) + (f2.x + f3.x);
                acc[2*q + 1] += (f0.y + f1.y) + (f2.y + f3.y);
            }
        }
        for (; t < cnt; t++) {
            int j = __shfl_sync(0xffffffffu, nidx, t);
            uint4 w = *reinterpret_cast<const uint4*>(g_h2 + (size_t)j * D + lane * 8);
            const __half2* hv = reinterpret_cast<const __half2*>(&w);
#pragma unroll
            for (int q = 0; q < 4; q++) {
                float2 f = __half22float2(hv[q]);
                acc[2*q + 0] += f.x;
                acc[2*q + 1] += f.y;
            }
        }
    }

    float r = g_drs[i];
    float4 v0 = make_float4(acc[0]*r, acc[1]*r, acc[2]*r, acc[3]*r);
    float4 v1 = make_float4(acc[4]*r, acc[5]*r, acc[6]*r, acc[7]*r);
    float* orow = out + (size_t)i * D + lane * 8;
    *reinterpret_cast<float4*>(orow)     = v0;
    *reinterpret_cast<float4*>(orow + 4) = v1;
}

// ---------------------------------------------------------------------------
// Launch: cnt -> scan1 (drs ready), then GEMM || (scan2/3 + build_col), join.
// ---------------------------------------------------------------------------
extern "C" void kernel_launch(void* const* d_in, const int* in_sizes, int n_in,
                              void* d_out, int out_size) {
    const float* x  = (const float*)d_in[0];   // [N,256]
    const float* W  = (const float*)d_in[1];   // [256,256]
    const int*   ei = (const int*)d_in[2];     // [2,E]

    int N = in_sizes[0] / D;
    int E = in_sizes[2] / 2;
    const int* src = ei;
    const int* dst = ei + E;
    float* out = (float*)d_out;

    int nbN = (N + 255) / 256;
    int nbE = (E + 255) / 256;

    // Persistent side stream + events (host handles only; created once).
    static cudaStream_t s2 = nullptr;
    static cudaEvent_t evFork = nullptr, evJoin = nullptr;
    if (s2 == nullptr) {
        cudaStreamCreateWithFlags(&s2, cudaStreamNonBlocking);
        cudaEventCreateWithFlags(&evFork, cudaEventDisableTiming);
        cudaEventCreateWithFlags(&evJoin, cudaEventDisableTiming);
    }

    // Stage 1 (main stream): degree histogram + scan_phase1 -> drs ready.
    cnt_zero   <<<nbN, 256>>>(N);
    cnt_edges  <<<nbE, 256>>>(src, E);
    scan_phase1<<<nbN, 256>>>(N);

    // Fork: GEMM (needs drs only) runs on s2 ...
    cudaEventRecord(evFork, 0);
    cudaStreamWaitEvent(s2, evFork, 0);
    {
        dim3 grid(D / 128, (N + 127) / 128);
        hgemm_abt<<<grid, 256, 0, s2>>>(x, W, N);
    }
    cudaEventRecord(evJoin, s2);

    // ... while the main stream finishes the CSR build.
    scan_phase2<<<1,   512>>>(nbN);
    scan_phase3<<<nbN, 256>>>(N, E);
    build_col  <<<nbE, 256>>>(src, dst, E);

    // Join: aggregate needs both h2 and the CSR.
    cudaStreamWaitEvent(0, evJoin, 0);
    aggregate<<<(N + 7) / 8, 256>>>(out, N);
}

// round 7
// speedup vs baseline: 1.1205x; 1.0398x over previous
#include <cuda_runtime.h>
#include <cuda_fp16.h>
#include <cstdint>
#include <cstddef>

// Problem constants: N=100000, D_IN=D_OUT=256, E=3.2M
#define MAXN 100352
#define MAXE 3200000
#define D    256

// Scratch (device globals; allocation is forbidden)
__device__ __align__(16) __half g_h2[(size_t)MAXN * D];  // drs[j] * (x@W^T)[j], fp16
__device__ __align__(16) __half g_xh[(size_t)MAXN * D];  // fp16(x); rows >= N stay zero
__device__ __align__(16) __half g_wh[D * D];             // fp16(W)
__device__ float g_drs[MAXN];
__device__ int   g_cnt[MAXN];
__device__ int   g_excl[MAXN];
__device__ int   g_blksum[512];
__device__ int   g_rowptr[MAXN + 1];
__device__ int   g_off[MAXN];
__device__ int   g_col[MAXE];

__device__ __forceinline__ uint32_t smem_u32(const void* p) {
    return (uint32_t)__cvta_generic_to_shared(p);
}

__device__ __forceinline__ void cp_cg16(uint32_t dst, const void* src) {
    asm volatile("cp.async.cg.shared.global [%0], [%1], 16;" :: "r"(dst), "l"(src));
}

template<int NPend>
__device__ __forceinline__ void cp_wait() {
    asm volatile("cp.async.wait_group %0;" :: "n"(NPend) : "memory");
}

// ---------------------------------------------------------------------------
// fp32 -> fp16 bulk convert (8 floats / thread)
// ---------------------------------------------------------------------------
__global__ void cvt_f2h(const float* __restrict__ in, __half* __restrict__ out, int n8) {
    int i = blockIdx.x * blockDim.x + threadIdx.x;
    if (i >= n8) return;
    float4 a = reinterpret_cast<const float4*>(in)[2 * i];
    float4 b = reinterpret_cast<const float4*>(in)[2 * i + 1];
    __half2 h[4];
    h[0] = __floats2half2_rn(a.x, a.y);
    h[1] = __floats2half2_rn(a.z, a.w);
    h[2] = __floats2half2_rn(b.x, b.y);
    h[3] = __floats2half2_rn(b.z, b.w);
    reinterpret_cast<uint4*>(out)[i] = *reinterpret_cast<uint4*>(h);
}

// ---------------------------------------------------------------------------
// Degree histogram
// ---------------------------------------------------------------------------
__global__ void cnt_zero(int N) {
    int i = blockIdx.x * blockDim.x + threadIdx.x;
    if (i < N) g_cnt[i] = 0;
}

__global__ void cnt_edges(const int* __restrict__ src, int E) {
    int e = blockIdx.x * blockDim.x + threadIdx.x;
    if (e < E) atomicAdd(&g_cnt[src[e]], 1);
}

// ---------------------------------------------------------------------------
// Prefix sum over g_cnt -> g_rowptr (+ fused drs = rsqrt(deg+1))
// ---------------------------------------------------------------------------
__global__ void scan_phase1(int N) {
    __shared__ int sh[256];
    int i = blockIdx.x * 256 + threadIdx.x;
    int v = (i < N) ? g_cnt[i] : 0;
    if (i < N) g_drs[i] = rsqrtf((float)v + 1.0f);
    sh[threadIdx.x] = v;
    __syncthreads();
#pragma unroll
    for (int off = 1; off < 256; off <<= 1) {
        int t = (threadIdx.x >= off) ? sh[threadIdx.x - off] : 0;
        __syncthreads();
        sh[threadIdx.x] += t;
        __syncthreads();
    }
    if (i < N) g_excl[i] = sh[threadIdx.x] - v;
    if (threadIdx.x == 255) g_blksum[blockIdx.x] = sh[255];
}

__global__ void scan_phase2(int nb) {
    __shared__ int sh[512];
    int t = threadIdx.x;
    int v = (t < nb) ? g_blksum[t] : 0;
    sh[t] = v;
    __syncthreads();
#pragma unroll
    for (int off = 1; off < 512; off <<= 1) {
        int u = (t >= off) ? sh[t - off] : 0;
        __syncthreads();
        sh[t] += u;
        __syncthreads();
    }
    if (t < nb) g_blksum[t] = sh[t] - v;
}

__global__ void scan_phase3(int N, int E) {
    int i = blockIdx.x * 256 + threadIdx.x;
    if (i < N) {
        int r = g_excl[i] + g_blksum[blockIdx.x];
        g_rowptr[i] = r;
        g_off[i] = r;
    }
    if (i == 0) g_rowptr[N] = E;
}

__global__ void build_col(const int* __restrict__ src, const int* __restrict__ dst, int E) {
    int e = blockIdx.x * blockDim.x + threadIdx.x;
    if (e < E) {
        int p = atomicAdd(&g_off[src[e]], 1);
        g_col[p] = dst[e];
    }
}

// ---------------------------------------------------------------------------
// cp.async 3-stage pipelined HGEMM (fp16 in, fp32 acc):
//   g_h2 = fp16( drs[i] * (xh @ wh^T) )
// 128x128 block tile, BK=32, 8 warps (2x4 layout), 80B smem row stride.
// ---------------------------------------------------------------------------
#define BK      32
#define STRIDE  40                  // halves per smem row (80B, 16B-aligned, conflict-free)
#define TILEH   (128 * STRIDE)      // halves per tile buffer
#define STAGES  3

__global__ void __launch_bounds__(256, 2) hgemm16(const __half* __restrict__ Ah,
                                                  const __half* __restrict__ Bh,
                                                  int M) {
    extern __shared__ __half smemraw[];   // STAGES * 2 * TILEH halves

    const int tid  = threadIdx.x;
    const int lane = tid & 31;
    const int wid  = tid >> 5;
    const int wm   = wid >> 2;       // 0..1
    const int wn   = wid & 3;        // 0..3
    const int brow = blockIdx.y * 128;
    const int bcol = blockIdx.x * 128;

    float acc[4][4][4];
#pragma unroll
    for (int mt = 0; mt < 4; mt++)
#pragma unroll
        for (int nt = 0; nt < 4; nt++)
#pragma unroll
            for (int q = 0; q < 4; q++) acc[mt][nt][q] = 0.0f;

    // Per-thread load chunks: 512 x 16B per tile, 2 per thread per matrix.
    const int c0r = (tid)       >> 2, c0s = ((tid)       & 3) * 8;
    const int c1r = (tid + 256) >> 2, c1s = ((tid + 256) & 3) * 8;

    auto load_stage = [&](int st, int k0) {
        __half* As = smemraw + st * 2 * TILEH;
        __half* Bs = As + TILEH;
        cp_cg16(smem_u32(As + c0r * STRIDE + c0s), Ah + (size_t)(brow + c0r) * 256 + k0 + c0s);
        cp_cg16(smem_u32(Bs + c0r * STRIDE + c0s), Bh + (size_t)(bcol + c0r) * 256 + k0 + c0s);
        cp_cg16(smem_u32(As + c1r * STRIDE + c1s), Ah + (size_t)(brow + c1r) * 256 + k0 + c1s);
        cp_cg16(smem_u32(Bs + c1r * STRIDE + c1s), Bh + (size_t)(bcol + c1r) * 256 + k0 + c1s);
        asm volatile("cp.async.commit_group;" ::: "memory");
    };

    auto compute_stage = [&](int st) {
        __half* As = smemraw + st * 2 * TILEH;
        __half* Bs = As + TILEH;
#pragma unroll
        for (int ks = 0; ks < 2; ks++) {
            uint32_t a[4][4], b[4][2];
#pragma unroll
            for (int mt = 0; mt < 4; mt++) {
                uint32_t addr = smem_u32(As + (wm * 64 + mt * 16 + (lane & 15)) * STRIDE
                                            + ks * 16 + (lane >> 4) * 8);
                asm volatile("ldmatrix.sync.aligned.m8n8.x4.shared.b16 {%0,%1,%2,%3}, [%4];"
                             : "=r"(a[mt][0]), "=r"(a[mt][1]), "=r"(a[mt][2]), "=r"(a[mt][3])
                             : "r"(addr));
            }
#pragma unroll
            for (int nt = 0; nt < 4; nt++) {
                int l16 = lane & 15;
                uint32_t addr = smem_u32(Bs + (wn * 32 + nt * 8 + (l16 & 7)) * STRIDE
                                            + ks * 16 + (l16 >> 3) * 8);
                asm volatile("ldmatrix.sync.aligned.m8n8.x2.shared.b16 {%0,%1}, [%2];"
                             : "=r"(b[nt][0]), "=r"(b[nt][1])
                             : "r"(addr));
            }
#pragma unroll
            for (int mt = 0; mt < 4; mt++)
#pragma unroll
                for (int nt = 0; nt < 4; nt++)
                    asm volatile(
                        "mma.sync.aligned.m16n8k16.row.col.f32.f16.f16.f32 "
                        "{%0,%1,%2,%3},{%4,%5,%6,%7},{%8,%9},{%0,%1,%2,%3};"
                        : "+f"(acc[mt][nt][0]), "+f"(acc[mt][nt][1]),
                          "+f"(acc[mt][nt][2]), "+f"(acc[mt][nt][3])
                        : "r"(a[mt][0]), "r"(a[mt][1]), "r"(a[mt][2]), "r"(a[mt][3]),
                          "r"(b[nt][0]), "r"(b[nt][1]));
        }
    };

    // Prologue: fill 2 stages.
    load_stage(0, 0);
    load_stage(1, BK);

    // Mainloop: 8 iterations of BK=32.
#pragma unroll
    for (int it = 0; it < 8; it++) {
        if (it + 2 < 8) load_stage((it + 2) % STAGES, (it + 2) * BK);
        if (it < 6)      cp_wait<2>();
        else if (it == 6) cp_wait<1>();
        else              cp_wait<0>();
        __syncthreads();
        compute_stage(it % STAGES);
        __syncthreads();
    }

    // Epilogue: scale rows by drs, convert fp16, store to g_h2.
    const int tg = lane >> 2, tq = lane & 3;
#pragma unroll
    for (int mt = 0; mt < 4; mt++) {
        int r0 = brow + wm * 64 + mt * 16 + tg;
        int r1 = r0 + 8;
        float s0 = (r0 < M) ? g_drs[r0] : 0.f;
        float s1 = (r1 < M) ? g_drs[r1] : 0.f;
#pragma unroll
        for (int nt = 0; nt < 4; nt++) {
            int c = bcol + wn * 32 + nt * 8 + tq * 2;
            if (r0 < M)
                *reinterpret_cast<__half2*>(g_h2 + (size_t)r0 * D + c) =
                    __floats2half2_rn(acc[mt][nt][0] * s0, acc[mt][nt][1] * s0);
            if (r1 < M)
                *reinterpret_cast<__half2*>(g_h2 + (size_t)r1 * D + c) =
                    __floats2half2_rn(acc[mt][nt][2] * s1, acc[mt][nt][3] * s1);
        }
    }
}

// ---------------------------------------------------------------------------
// Aggregation: one warp per node, 4-way unrolled gather (h2 prescaled by drs).
// out[i] = drs[i] * ( h2[i] + sum_{j in adj(i)} h2[j] )
// ---------------------------------------------------------------------------
__global__ void __launch_bounds__(256) aggregate(float* __restrict__ out, int N) {
    int warp = (blockIdx.x * blockDim.x + threadIdx.x) >> 5;
    int lane = threadIdx.x & 31;
    if (warp >= N) return;
    const int i = warp;

    float acc[8];
    {   // self loop
        uint4 w = *reinterpret_cast<const uint4*>(g_h2 + (size_t)i * D + lane * 8);
        const __half2* hv = reinterpret_cast<const __half2*>(&w);
#pragma unroll
        for (int q = 0; q < 4; q++) {
            float2 f = __half22float2(hv[q]);
            acc[2*q + 0] = f.x;
            acc[2*q + 1] = f.y;
        }
    }

    int s = g_rowptr[i];
    int e = g_rowptr[i + 1];
    for (int b = s; b < e; b += 32) {
        int nidx = (b + lane < e) ? g_col[b + lane] : 0;
        int cnt = min(32, e - b);
        int t = 0;
        for (; t + 4 <= cnt; t += 4) {
            int j0 = __shfl_sync(0xffffffffu, nidx, t + 0);
            int j1 = __shfl_sync(0xffffffffu, nidx, t + 1);
            int j2 = __shfl_sync(0xffffffffu, nidx, t + 2);
            int j3 = __shfl_sync(0xffffffffu, nidx, t + 3);
            uint4 w0 = *reinterpret_cast<const uint4*>(g_h2 + (size_t)j0 * D + lane * 8);
            uint4 w1 = *reinterpret_cast<const uint4*>(g_h2 + (size_t)j1 * D + lane * 8);
            uint4 w2 = *reinterpret_cast<const uint4*>(g_h2 + (size_t)j2 * D + lane * 8);
            uint4 w3 = *reinterpret_cast<const uint4*>(g_h2 + (size_t)j3 * D + lane * 8);
            const __half2* h0 = reinterpret_cast<const __half2*>(&w0);
            const __half2* h1 = reinterpret_cast<const __half2*>(&w1);
            const __half2* h2 = reinterpret_cast<const __half2*>(&w2);
            const __half2* h3 = reinterpret_cast<const __half2*>(&w3);
#pragma unroll
            for (int q = 0; q < 4; q++) {
                float2 f0 = __half22float2(h0[q]);
                float2 f1 = __half22float2(h1[q]);
                float2 f2 = __half22float2(h2[q]);
                float2 f3 = __half22float2(h3[q]);
                acc[2*q + 0] += (f0.x + f1.x) + (f2.x + f3.x);
                acc[2*q + 1] += (f0.y + f1.y) + (f2.y + f3.y);
            }
        }
        for (; t < cnt; t++) {
            int j = __shfl_sync(0xffffffffu, nidx, t);
            uint4 w = *reinterpret_cast<const uint4*>(g_h2 + (size_t)j * D + lane * 8);
            const __half2* hv = reinterpret_cast<const __half2*>(&w);
#pragma unroll
            for (int q = 0; q < 4; q++) {
                float2 f = __half22float2(hv[q]);
                acc[2*q + 0] += f.x;
                acc[2*q + 1] += f.y;
            }
        }
    }

    float r = g_drs[i];
    float4 v0 = make_float4(acc[0]*r, acc[1]*r, acc[2]*r, acc[3]*r);
    float4 v1 = make_float4(acc[4]*r, acc[5]*r, acc[6]*r, acc[7]*r);
    float* orow = out + (size_t)i * D + lane * 8;
    *reinterpret_cast<float4*>(orow)     = v0;
    *reinterpret_cast<float4*>(orow + 4) = v1;
}

// ---------------------------------------------------------------------------
// Launch: (convert x,W on s2) || (cnt -> scan1); GEMM on s2 after scan1;
//         (scan2/3 + build_col) on main; join -> aggregate.
// ---------------------------------------------------------------------------
extern "C" void kernel_launch(void* const* d_in, const int* in_sizes, int n_in,
                              void* d_out, int out_size) {
    const float* x  = (const float*)d_in[0];   // [N,256]
    const float* W  = (const float*)d_in[1];   // [256,256]
    const int*   ei = (const int*)d_in[2];     // [2,E]

    int N = in_sizes[0] / D;
    int E = in_sizes[2] / 2;
    const int* src = ei;
    const int* dst = ei + E;
    float* out = (float*)d_out;

    int nbN = (N + 255) / 256;
    int nbE = (E + 255) / 256;

    static cudaStream_t s2 = nullptr;
    static cudaEvent_t evFork = nullptr, evDrs = nullptr, evJoin = nullptr;
    if (s2 == nullptr) {
        cudaStreamCreateWithFlags(&s2, cudaStreamNonBlocking);
        cudaEventCreateWithFlags(&evFork, cudaEventDisableTiming);
        cudaEventCreateWithFlags(&evDrs, cudaEventDisableTiming);
        cudaEventCreateWithFlags(&evJoin, cudaEventDisableTiming);
        cudaFuncSetAttribute(hgemm16, cudaFuncAttributeMaxDynamicSharedMemorySize,
                             STAGES * 2 * TILEH * (int)sizeof(__half));
    }

    __half* xh = nullptr;
    __half* wh = nullptr;
    cudaGetSymbolAddress((void**)&xh, g_xh);
    cudaGetSymbolAddress((void**)&wh, g_wh);

    // Fork at entry: conversions run on s2 while main builds the histogram.
    cudaEventRecord(evFork, 0);
    cudaStreamWaitEvent(s2, evFork, 0);
    cvt_f2h<<<(N * 32 + 255) / 256, 256, 0, s2>>>(x, xh, N * 32);      // N*256/8
    cvt_f2h<<<(D * 32 + 255) / 256, 256, 0, s2>>>(W, wh, D * 32);      // 8192

    // Main: degree histogram + scan_phase1 -> drs ready.
    cnt_zero   <<<nbN, 256>>>(N);
    cnt_edges  <<<nbE, 256>>>(src, E);
    scan_phase1<<<nbN, 256>>>(N);
    cudaEventRecord(evDrs, 0);

    // GEMM on s2 (needs xh, wh, drs).
    cudaStreamWaitEvent(s2, evDrs, 0);
    {
        dim3 grid(D / 128, (N + 127) / 128);
        hgemm16<<<grid, 256, STAGES * 2 * TILEH * (int)sizeof(__half), s2>>>(xh, wh, N);
    }
    cudaEventRecord(evJoin, s2);

    // Main: finish CSR build in parallel with the GEMM.
    scan_phase2<<<1,   512>>>(nbN);
    scan_phase3<<<nbN, 256>>>(N, E);
    build_col  <<<nbE, 256>>>(src, dst, E);

    // Join: aggregate needs both h2 and the CSR.
    cudaStreamWaitEvent(0, evJoin, 0);
    aggregate<<<(N + 7) / 8, 256>>>(out, N);
}